// round 1
// baseline (speedup 1.0000x reference)
#include <cuda_runtime.h>
#include <math.h>

#define B_ 2
#define T_ 2048
#define C_ 1024
#define H_ 16
#define HS_ 64

// Scratch (allocation-free rule: __device__ globals)
__device__ float g_q[B_ * T_ * C_];
__device__ float g_k[B_ * T_ * HS_];
__device__ float g_v[B_ * T_ * HS_];
__device__ float g_y[B_ * T_ * C_];

// C[m,n] = sum_k A[m,k] * W[n,k] (+ bias[n])
// A: [M,K] row-major, W: [N,K] row-major (torch Linear weight). M from grid.y*64.
// Requires M%64==0, N%64==0, K%16==0 (true for all uses here).
template <bool BIAS>
__global__ __launch_bounds__(256) void gemm_nt(const float* __restrict__ A,
                                               const float* __restrict__ W,
                                               const float* __restrict__ bias,
                                               float* __restrict__ C,
                                               int N, int K) {
    __shared__ float As[16][65];
    __shared__ float Bs[16][65];
    int tid = threadIdx.x;
    int bm = blockIdx.y * 64, bn = blockIdx.x * 64;
    int tx = tid & 15, ty = tid >> 4;
    int lr = tid >> 2, lk = (tid & 3) * 4;
    float acc[4][4] = {};
    const float* Ag = A + (size_t)(bm + lr) * K + lk;
    const float* Wg = W + (size_t)(bn + lr) * K + lk;
    for (int k0 = 0; k0 < K; k0 += 16) {
        float4 a = *(const float4*)(Ag + k0);
        float4 b = *(const float4*)(Wg + k0);
        As[lk + 0][lr] = a.x; As[lk + 1][lr] = a.y;
        As[lk + 2][lr] = a.z; As[lk + 3][lr] = a.w;
        Bs[lk + 0][lr] = b.x; Bs[lk + 1][lr] = b.y;
        Bs[lk + 2][lr] = b.z; Bs[lk + 3][lr] = b.w;
        __syncthreads();
#pragma unroll
        for (int kk = 0; kk < 16; kk++) {
            float ra[4], rb[4];
#pragma unroll
            for (int i = 0; i < 4; i++) {
                ra[i] = As[kk][ty * 4 + i];
                rb[i] = Bs[kk][tx * 4 + i];
            }
#pragma unroll
            for (int i = 0; i < 4; i++)
#pragma unroll
                for (int j = 0; j < 4; j++)
                    acc[i][j] = fmaf(ra[i], rb[j], acc[i][j]);
        }
        __syncthreads();
    }
#pragma unroll
    for (int i = 0; i < 4; i++) {
#pragma unroll
        for (int j = 0; j < 4; j++) {
            float v = acc[i][j];
            if (BIAS) v += bias[bn + tx * 4 + j];
            C[(size_t)(bm + ty * 4 + i) * N + bn + tx * 4 + j] = v;
        }
    }
}

// Flash-style causal MQA attention.
// One query row per thread. q remap quirk: q[b,h,t,:] = q_orig[b, h*128 + t/16, (t%16)*64 .. +64).
// Output written transposed into y[b, t, h*64 + d].
__global__ __launch_bounds__(128) void attn_kernel(const float* __restrict__ q,
                                                   const float* __restrict__ k,
                                                   const float* __restrict__ v,
                                                   float* __restrict__ y) {
    __shared__ __align__(16) float Ks[64][64];
    __shared__ __align__(16) float Vs[64][64];
    int qt = blockIdx.x;       // 0..15 (T/128 query tiles)
    int bh = blockIdx.y;       // 0..31
    int b = bh >> 4, h = bh & 15;
    int tid = threadIdx.x;
    int tq = qt * 128 + tid;

    // Load this thread's (remapped) query row into registers.
    const float* qrow = q + (size_t)(b * T_ + h * 128 + (tq >> 4)) * C_ + (tq & 15) * HS_;
    float qr[64];
#pragma unroll
    for (int i = 0; i < 16; i++) {
        float4 t4 = *(const float4*)(qrow + i * 4);
        qr[i * 4 + 0] = t4.x; qr[i * 4 + 1] = t4.y;
        qr[i * 4 + 2] = t4.z; qr[i * 4 + 3] = t4.w;
    }

    float o[64];
#pragma unroll
    for (int d = 0; d < 64; d++) o[d] = 0.f;
    float mi = -INFINITY, li = 0.f;

    const float4* kb = (const float4*)(k + (size_t)b * T_ * HS_);
    const float4* vb = (const float4*)(v + (size_t)b * T_ * HS_);

    int nkt = qt * 2 + 2;  // causal: only K tiles overlapping [0, qt*128+127]
    for (int kt = 0; kt < nkt; kt++) {
        __syncthreads();
        // Stage K/V tile (64 rows x 64 floats = 1024 float4 each; 8 per thread)
#pragma unroll
        for (int i = 0; i < 8; i++) {
            int idx = tid + i * 128;
            ((float4*)Ks)[idx] = kb[kt * 1024 + idx];
            ((float4*)Vs)[idx] = vb[kt * 1024 + idx];
        }
        __syncthreads();
#pragma unroll 1
        for (int c = 0; c < 4; c++) {
            int tkb = kt * 64 + c * 16;
            if (tkb > tq) break;  // fully-masked chunk (and all later chunks)
            float s[16];
#pragma unroll
            for (int j = 0; j < 16; j++) {
                const float4* kr = (const float4*)Ks[c * 16 + j];
                float acc = 0.f;
#pragma unroll
                for (int d4 = 0; d4 < 16; d4++) {
                    float4 kv = kr[d4];  // broadcast LDS.128 across warp
                    acc = fmaf(qr[d4 * 4 + 0], kv.x, acc);
                    acc = fmaf(qr[d4 * 4 + 1], kv.y, acc);
                    acc = fmaf(qr[d4 * 4 + 2], kv.z, acc);
                    acc = fmaf(qr[d4 * 4 + 3], kv.w, acc);
                }
                s[j] = (tkb + j <= tq) ? acc * 0.125f : -INFINITY;
            }
            float cmax = s[0];
#pragma unroll
            for (int j = 1; j < 16; j++) cmax = fmaxf(cmax, s[j]);
            float mnew = fmaxf(mi, cmax);
            float corr = __expf(mi - mnew);  // first chunk: exp(-inf)=0, o is zero anyway
            li *= corr;
#pragma unroll
            for (int d = 0; d < 64; d++) o[d] *= corr;
#pragma unroll
            for (int j = 0; j < 16; j++) {
                float p = __expf(s[j] - mnew);  // masked lanes -> 0
                li += p;
                const float4* vr = (const float4*)Vs[c * 16 + j];
#pragma unroll
                for (int d4 = 0; d4 < 16; d4++) {
                    float4 vv = vr[d4];
                    o[d4 * 4 + 0] = fmaf(p, vv.x, o[d4 * 4 + 0]);
                    o[d4 * 4 + 1] = fmaf(p, vv.y, o[d4 * 4 + 1]);
                    o[d4 * 4 + 2] = fmaf(p, vv.z, o[d4 * 4 + 2]);
                    o[d4 * 4 + 3] = fmaf(p, vv.w, o[d4 * 4 + 3]);
                }
            }
            mi = mnew;
        }
    }

    float inv = 1.f / li;  // li > 0: diagonal key always present
    float* yo = y + (size_t)(b * T_ + tq) * C_ + h * HS_;
#pragma unroll
    for (int d4 = 0; d4 < 16; d4++) {
        float4 t4;
        t4.x = o[d4 * 4 + 0] * inv;
        t4.y = o[d4 * 4 + 1] * inv;
        t4.z = o[d4 * 4 + 2] * inv;
        t4.w = o[d4 * 4 + 3] * inv;
        *(float4*)(yo + d4 * 4) = t4;
    }
}

extern "C" void kernel_launch(void* const* d_in, const int* in_sizes, int n_in,
                              void* d_out, int out_size) {
    (void)in_sizes; (void)n_in; (void)out_size;
    const float* x  = (const float*)d_in[0];
    const float* Wk = (const float*)d_in[1];
    const float* Wv = (const float*)d_in[2];
    const float* Wq = (const float*)d_in[3];
    const float* Wp = (const float*)d_in[4];
    const float* bp = (const float*)d_in[5];
    float* out = (float*)d_out;

    float *qb, *kb, *vb, *yb;
    cudaGetSymbolAddress((void**)&qb, g_q);
    cudaGetSymbolAddress((void**)&kb, g_k);
    cudaGetSymbolAddress((void**)&vb, g_v);
    cudaGetSymbolAddress((void**)&yb, g_y);

    dim3 blk(256);
    // q = x @ Wq.T : [4096,1024]
    gemm_nt<false><<<dim3(16, 64), blk>>>(x, Wq, nullptr, qb, 1024, 1024);
    // k = x @ Wk.T, v = x @ Wv.T : [4096,64]
    gemm_nt<false><<<dim3(1, 64), blk>>>(x, Wk, nullptr, kb, 64, 1024);
    gemm_nt<false><<<dim3(1, 64), blk>>>(x, Wv, nullptr, vb, 64, 1024);
    // attention -> y [B,T,C] (already head-transposed layout)
    attn_kernel<<<dim3(16, 32), 128>>>(qb, kb, vb, yb);
    // out = y @ Wp.T + bp
    gemm_nt<true><<<dim3(16, 64), blk>>>(yb, Wp, bp, out, 1024, 1024);
}

// round 2
// speedup vs baseline: 3.7178x; 3.7178x over previous
#include <cuda_runtime.h>
#include <math.h>
#include <stdint.h>

#define B_ 2
#define T_ 2048
#define C_ 1024
#define H_ 16
#define HS_ 64

// Scratch (allocation-free rule: __device__ globals)
__device__ float g_q[B_ * T_ * C_];
__device__ float g_k[B_ * T_ * HS_];
__device__ float g_v[B_ * T_ * HS_];
__device__ float g_y[B_ * T_ * C_];

__device__ __forceinline__ uint32_t f2tf(float f) {
    uint32_t u;
    asm("cvt.rna.tf32.f32 %0, %1;" : "=r"(u) : "f"(f));
    return u;
}

__device__ __forceinline__ void mma_tf32(float c[4], const uint32_t a[4], const uint32_t b[2]) {
    asm volatile(
        "mma.sync.aligned.m16n8k8.row.col.f32.tf32.tf32.f32 "
        "{%0,%1,%2,%3}, {%4,%5,%6,%7}, {%8,%9}, {%0,%1,%2,%3};"
        : "+f"(c[0]), "+f"(c[1]), "+f"(c[2]), "+f"(c[3])
        : "r"(a[0]), "r"(a[1]), "r"(a[2]), "r"(a[3]), "r"(b[0]), "r"(b[1]));
}

// C[m,n] = sum_k A[m,k] * W[n,k] (+bias), tf32 tensor cores.
// BM=128 fixed, BK=32, BN template. 256 threads = 8 warps (4m x 2n).
template <int BN, bool BIAS>
__global__ __launch_bounds__(256) void gemm_tc(const float* __restrict__ A,
                                               const float* __restrict__ W,
                                               const float* __restrict__ bias,
                                               float* __restrict__ C,
                                               int N, int K) {
    constexpr int NT = BN / 16;  // n-tiles (of 8) per warp
    __shared__ uint32_t As[128][36];
    __shared__ uint32_t Bs[BN][36];
    int tid = threadIdx.x, lane = tid & 31, warp = tid >> 5;
    int g = lane >> 2, q4 = lane & 3;
    int wm = warp & 3, wn = warp >> 2;
    int bm = blockIdx.y * 128, bn = blockIdx.x * BN;

    float acc[2][NT][4];
#pragma unroll
    for (int mt = 0; mt < 2; mt++)
#pragma unroll
        for (int j = 0; j < NT; j++)
#pragma unroll
            for (int e = 0; e < 4; e++) acc[mt][j][e] = 0.f;

    for (int k0 = 0; k0 < K; k0 += 32) {
        __syncthreads();
#pragma unroll
        for (int t = 0; t < 4; t++) {
            int idx = tid + t * 256;
            int r = idx >> 3, c4 = (idx & 7) * 4;
            float4 f = *(const float4*)&A[(size_t)(bm + r) * K + k0 + c4];
            *(uint4*)&As[r][c4] = make_uint4(f2tf(f.x), f2tf(f.y), f2tf(f.z), f2tf(f.w));
        }
#pragma unroll
        for (int t = 0; t < BN / 32; t++) {
            int idx = tid + t * 256;
            int r = idx >> 3, c4 = (idx & 7) * 4;
            float4 f = *(const float4*)&W[(size_t)(bn + r) * K + k0 + c4];
            *(uint4*)&Bs[r][c4] = make_uint4(f2tf(f.x), f2tf(f.y), f2tf(f.z), f2tf(f.w));
        }
        __syncthreads();
#pragma unroll
        for (int kk = 0; kk < 4; kk++) {
            uint32_t af[2][4], bf[NT][2];
#pragma unroll
            for (int mt = 0; mt < 2; mt++) {
                int rb = wm * 32 + mt * 16;
                af[mt][0] = As[rb + g][kk * 8 + q4];
                af[mt][1] = As[rb + g + 8][kk * 8 + q4];
                af[mt][2] = As[rb + g][kk * 8 + q4 + 4];
                af[mt][3] = As[rb + g + 8][kk * 8 + q4 + 4];
            }
#pragma unroll
            for (int j = 0; j < NT; j++) {
                int nb = wn * (BN / 2) + j * 8 + g;
                bf[j][0] = Bs[nb][kk * 8 + q4];
                bf[j][1] = Bs[nb][kk * 8 + q4 + 4];
            }
#pragma unroll
            for (int mt = 0; mt < 2; mt++)
#pragma unroll
                for (int j = 0; j < NT; j++) mma_tf32(acc[mt][j], af[mt], bf[j]);
        }
    }
#pragma unroll
    for (int mt = 0; mt < 2; mt++)
#pragma unroll
        for (int j = 0; j < NT; j++) {
            int row = bm + wm * 32 + mt * 16 + g;
            int col = bn + wn * (BN / 2) + j * 8 + 2 * q4;
            float2 v0 = make_float2(acc[mt][j][0], acc[mt][j][1]);
            float2 v1 = make_float2(acc[mt][j][2], acc[mt][j][3]);
            if (BIAS) {
                float b0 = bias[col], b1 = bias[col + 1];
                v0.x += b0; v0.y += b1; v1.x += b0; v1.y += b1;
            }
            *(float2*)&C[(size_t)row * N + col] = v0;
            *(float2*)&C[(size_t)(row + 8) * N + col] = v1;
        }
}

// Flash-style causal MQA attention, tf32 tensor cores.
// 256 thr = 8 warps; each warp owns 16 query rows (one m16 tile), 64-key tiles.
// q remap quirk: q[b,h,t,:] = q_orig[b, h*128 + t/16, (t%16)*64 .. +64).
__global__ __launch_bounds__(256) void attn_tc(const float* __restrict__ q,
                                               const float* __restrict__ k,
                                               const float* __restrict__ v,
                                               float* __restrict__ y) {
    __shared__ uint32_t Ks[64][68];  // [key][dim], pad4 -> conflict-free b-frag reads
    __shared__ uint32_t Vs[64][72];  // [key][dim], pad8
    int qt = blockIdx.x, bh = blockIdx.y;
    int b = bh >> 4, h = bh & 15;
    int tid = threadIdx.x, lane = tid & 31, warp = tid >> 5;
    int g = lane >> 2, q4 = lane & 3;
    int r0 = qt * 128 + warp * 16 + g;  // global query rows for this thread
    int r1 = r0 + 8;

    // Q fragments (remapped), pre-scaled by hs^-0.5 = 0.125
    uint32_t qa[8][4];
    const float* qb = q + (size_t)b * T_ * C_;
#pragma unroll
    for (int kk = 0; kk < 8; kk++) {
        int c0 = kk * 8 + q4;
        size_t a0 = (size_t)(h * 128 + (r0 >> 4)) * C_ + (r0 & 15) * 64;
        size_t a1 = (size_t)(h * 128 + (r1 >> 4)) * C_ + (r1 & 15) * 64;
        qa[kk][0] = f2tf(0.125f * qb[a0 + c0]);
        qa[kk][1] = f2tf(0.125f * qb[a1 + c0]);
        qa[kk][2] = f2tf(0.125f * qb[a0 + c0 + 4]);
        qa[kk][3] = f2tf(0.125f * qb[a1 + c0 + 4]);
    }

    float o[8][4];
#pragma unroll
    for (int j = 0; j < 8; j++)
#pragma unroll
        for (int e = 0; e < 4; e++) o[j][e] = 0.f;
    float m0 = -INFINITY, m1 = -INFINITY, l0 = 0.f, l1 = 0.f;

    const float* kb = k + (size_t)b * T_ * HS_;
    const float* vb = v + (size_t)b * T_ * HS_;
    int nkt = qt * 2 + 2;
    int wrmin = qt * 128 + warp * 16;
    int wrmax = wrmin + 15;
    int srcA = (lane & ~3) | (q4 >> 1);
    int srcB = srcA + 2;
    bool sel = (q4 & 1) != 0;

    for (int kt = 0; kt < nkt; kt++) {
        __syncthreads();
#pragma unroll
        for (int t = 0; t < 4; t++) {
            int idx = tid + t * 256;
            int r = idx >> 4, c4 = (idx & 15) * 4;
            float4 fk = *(const float4*)&kb[(size_t)(kt * 64 + r) * 64 + c4];
            *(uint4*)&Ks[r][c4] = make_uint4(f2tf(fk.x), f2tf(fk.y), f2tf(fk.z), f2tf(fk.w));
            float4 fv = *(const float4*)&vb[(size_t)(kt * 64 + r) * 64 + c4];
            *(uint4*)&Vs[r][c4] = make_uint4(f2tf(fv.x), f2tf(fv.y), f2tf(fv.z), f2tf(fv.w));
        }
        __syncthreads();
        int ktb = kt * 64;
        if (ktb > wrmax) continue;  // fully masked for this warp

        // S = Q K^T (pre-scaled)
        float s[8][4];
#pragma unroll
        for (int j = 0; j < 8; j++)
#pragma unroll
            for (int e = 0; e < 4; e++) s[j][e] = 0.f;
#pragma unroll
        for (int kk = 0; kk < 8; kk++) {
#pragma unroll
            for (int j = 0; j < 8; j++) {
                uint32_t bf[2];
                bf[0] = Ks[j * 8 + g][kk * 8 + q4];
                bf[1] = Ks[j * 8 + g][kk * 8 + q4 + 4];
                mma_tf32(s[j], qa[kk], bf);
            }
        }

        // mask + online softmax
        bool needmask = (ktb + 63) > wrmin;
        float t0 = -INFINITY, t1 = -INFINITY;
#pragma unroll
        for (int j = 0; j < 8; j++) {
            if (needmask) {
                int tk = ktb + j * 8 + 2 * q4;
                if (tk > r0) s[j][0] = -INFINITY;
                if (tk + 1 > r0) s[j][1] = -INFINITY;
                if (tk > r1) s[j][2] = -INFINITY;
                if (tk + 1 > r1) s[j][3] = -INFINITY;
            }
            t0 = fmaxf(t0, fmaxf(s[j][0], s[j][1]));
            t1 = fmaxf(t1, fmaxf(s[j][2], s[j][3]));
        }
        t0 = fmaxf(t0, __shfl_xor_sync(0xffffffffu, t0, 1));
        t0 = fmaxf(t0, __shfl_xor_sync(0xffffffffu, t0, 2));
        t1 = fmaxf(t1, __shfl_xor_sync(0xffffffffu, t1, 1));
        t1 = fmaxf(t1, __shfl_xor_sync(0xffffffffu, t1, 2));
        float mn0 = fmaxf(m0, t0), mn1 = fmaxf(m1, t1);
        float cr0 = __expf(m0 - mn0), cr1 = __expf(m1 - mn1);
        m0 = mn0; m1 = mn1;
        l0 *= cr0; l1 *= cr1;
#pragma unroll
        for (int j = 0; j < 8; j++) {
            o[j][0] *= cr0; o[j][1] *= cr0;
            o[j][2] *= cr1; o[j][3] *= cr1;
        }
        uint32_t pt[8][4];
#pragma unroll
        for (int j = 0; j < 8; j++) {
            float p0 = __expf(s[j][0] - m0);
            float p1 = __expf(s[j][1] - m0);
            float p2 = __expf(s[j][2] - m1);
            float p3 = __expf(s[j][3] - m1);
            l0 += p0 + p1;
            l1 += p2 + p3;
            pt[j][0] = f2tf(p0); pt[j][1] = f2tf(p1);
            pt[j][2] = f2tf(p2); pt[j][3] = f2tf(p3);
        }

        // O += P V  (C-frag -> A-frag via quad shuffles)
#pragma unroll
        for (int kk = 0; kk < 8; kk++) {
            uint32_t x0 = __shfl_sync(0xffffffffu, pt[kk][0], srcA);
            uint32_t x1 = __shfl_sync(0xffffffffu, pt[kk][1], srcA);
            uint32_t x2 = __shfl_sync(0xffffffffu, pt[kk][2], srcA);
            uint32_t x3 = __shfl_sync(0xffffffffu, pt[kk][3], srcA);
            uint32_t y0 = __shfl_sync(0xffffffffu, pt[kk][0], srcB);
            uint32_t y1 = __shfl_sync(0xffffffffu, pt[kk][1], srcB);
            uint32_t y2 = __shfl_sync(0xffffffffu, pt[kk][2], srcB);
            uint32_t y3 = __shfl_sync(0xffffffffu, pt[kk][3], srcB);
            uint32_t pa[4];
            pa[0] = sel ? x1 : x0;
            pa[1] = sel ? x3 : x2;
            pa[2] = sel ? y1 : y0;
            pa[3] = sel ? y3 : y2;
#pragma unroll
            for (int j = 0; j < 8; j++) {
                uint32_t bf[2];
                bf[0] = Vs[kk * 8 + q4][j * 8 + g];
                bf[1] = Vs[kk * 8 + q4 + 4][j * 8 + g];
                mma_tf32(o[j], pa, bf);
            }
        }
    }

    l0 += __shfl_xor_sync(0xffffffffu, l0, 1);
    l0 += __shfl_xor_sync(0xffffffffu, l0, 2);
    l1 += __shfl_xor_sync(0xffffffffu, l1, 1);
    l1 += __shfl_xor_sync(0xffffffffu, l1, 2);
    float i0 = 1.f / l0, i1 = 1.f / l1;
    float* yb = y + (size_t)b * T_ * C_;
#pragma unroll
    for (int j = 0; j < 8; j++) {
        int col = h * 64 + j * 8 + 2 * q4;
        *(float2*)&yb[(size_t)r0 * C_ + col] = make_float2(o[j][0] * i0, o[j][1] * i0);
        *(float2*)&yb[(size_t)r1 * C_ + col] = make_float2(o[j][2] * i1, o[j][3] * i1);
    }
}

extern "C" void kernel_launch(void* const* d_in, const int* in_sizes, int n_in,
                              void* d_out, int out_size) {
    (void)in_sizes; (void)n_in; (void)out_size;
    const float* x  = (const float*)d_in[0];
    const float* Wk = (const float*)d_in[1];
    const float* Wv = (const float*)d_in[2];
    const float* Wq = (const float*)d_in[3];
    const float* Wp = (const float*)d_in[4];
    const float* bp = (const float*)d_in[5];
    float* out = (float*)d_out;

    float *qb, *kb, *vb, *yb;
    cudaGetSymbolAddress((void**)&qb, g_q);
    cudaGetSymbolAddress((void**)&kb, g_k);
    cudaGetSymbolAddress((void**)&vb, g_v);
    cudaGetSymbolAddress((void**)&yb, g_y);

    // q = x @ Wq.T : [4096,1024]
    gemm_tc<128, false><<<dim3(8, 32), 256>>>(x, Wq, nullptr, qb, 1024, 1024);
    // k, v = x @ Wk.T / x @ Wv.T : [4096,64]
    gemm_tc<64, false><<<dim3(1, 32), 256>>>(x, Wk, nullptr, kb, 64, 1024);
    gemm_tc<64, false><<<dim3(1, 32), 256>>>(x, Wv, nullptr, vb, 64, 1024);
    // attention -> y [B,T,C] (head-transposed layout baked in)
    attn_tc<<<dim3(16, 32), 256>>>(qb, kb, vb, yb);
    // out = y @ Wp.T + bp
    gemm_tc<128, true><<<dim3(8, 32), 256>>>(yb, Wp, bp, out, 1024, 1024);
}

// round 3
// speedup vs baseline: 6.1457x; 1.6531x over previous
#include <cuda_runtime.h>
#include <math.h>
#include <stdint.h>

#define B_ 2
#define T_ 2048
#define C_ 1024
#define H_ 16
#define HS_ 64
#define NQKV 1152  // 1024 q + 64 k + 64 v

// Scratch (allocation-free rule: __device__ globals)
__device__ float g_wqkv[NQKV * C_];        // Wq ‖ Wk ‖ Wv
__device__ float g_qkv[B_ * T_ * NQKV];    // fused projection output
__device__ float g_y[B_ * T_ * C_];

__device__ __forceinline__ uint32_t f2tf(float f) {
    uint32_t u;
    asm("cvt.rna.tf32.f32 %0, %1;" : "=r"(u) : "f"(f));
    return u;
}

__device__ __forceinline__ void mma_tf32(float c[4], const uint32_t a[4], const uint32_t b[2]) {
    asm volatile(
        "mma.sync.aligned.m16n8k8.row.col.f32.tf32.tf32.f32 "
        "{%0,%1,%2,%3}, {%4,%5,%6,%7}, {%8,%9}, {%0,%1,%2,%3};"
        : "+f"(c[0]), "+f"(c[1]), "+f"(c[2]), "+f"(c[3])
        : "r"(a[0]), "r"(a[1]), "r"(a[2]), "r"(a[3]), "r"(b[0]), "r"(b[1]));
}

// Concat Wq(1024 rows) ‖ Wk(64) ‖ Wv(64), each row 1024 floats = 256 float4.
__global__ __launch_bounds__(256) void copy_w(const float* __restrict__ Wq,
                                              const float* __restrict__ Wk,
                                              const float* __restrict__ Wv,
                                              float* __restrict__ Wout) {
    int f = blockIdx.x * 1024 + threadIdx.x * 4;
#pragma unroll
    for (int t = 0; t < 4; t++) {
        int idx = f + t;  // float4 index
        int r = idx >> 8, c = idx & 255;
        const float* src = (r < 1024) ? Wq + (size_t)r * C_
                         : (r < 1088) ? Wk + (size_t)(r - 1024) * C_
                                      : Wv + (size_t)(r - 1088) * C_;
        ((float4*)Wout)[idx] = ((const float4*)src)[c];
    }
}

// C[m,n] = sum_k A[m,k] * W[n,k] (+bias), tf32 tensor cores.
// BM=128, BK=32, BN=128. 256 threads = 8 warps (4m x 2n). Register-prefetch pipelined.
template <bool BIAS>
__global__ __launch_bounds__(256) void gemm_tc(const float* __restrict__ A,
                                               const float* __restrict__ W,
                                               const float* __restrict__ bias,
                                               float* __restrict__ C,
                                               int N, int K) {
    __shared__ uint32_t As[128][36];
    __shared__ uint32_t Bs[128][36];
    int tid = threadIdx.x, lane = tid & 31, warp = tid >> 5;
    int g = lane >> 2, q4 = lane & 3;
    int wm = warp & 3, wn = warp >> 2;
    int bm = blockIdx.y * 128, bn = blockIdx.x * 128;
    int lr = tid >> 3, lc4 = (tid & 7) * 4;

    float acc[2][8][4];
#pragma unroll
    for (int mt = 0; mt < 2; mt++)
#pragma unroll
        for (int j = 0; j < 8; j++)
#pragma unroll
            for (int e = 0; e < 4; e++) acc[mt][j][e] = 0.f;

    const float* Ag = A + (size_t)(bm + lr) * K + lc4;
    const float* Wg = W + (size_t)(bn + lr) * K + lc4;

    float4 pa[4], pb[4];
#pragma unroll
    for (int t = 0; t < 4; t++) {
        pa[t] = *(const float4*)(Ag + (size_t)t * 32 * K);
        pb[t] = *(const float4*)(Wg + (size_t)t * 32 * K);
    }

    for (int k0 = 0; k0 < K; k0 += 32) {
#pragma unroll
        for (int t = 0; t < 4; t++) {
            *(uint4*)&As[lr + t * 32][lc4] =
                make_uint4(f2tf(pa[t].x), f2tf(pa[t].y), f2tf(pa[t].z), f2tf(pa[t].w));
            *(uint4*)&Bs[lr + t * 32][lc4] =
                make_uint4(f2tf(pb[t].x), f2tf(pb[t].y), f2tf(pb[t].z), f2tf(pb[t].w));
        }
        __syncthreads();
        if (k0 + 32 < K) {
#pragma unroll
            for (int t = 0; t < 4; t++) {
                pa[t] = *(const float4*)(Ag + (size_t)t * 32 * K + k0 + 32);
                pb[t] = *(const float4*)(Wg + (size_t)t * 32 * K + k0 + 32);
            }
        }
#pragma unroll
        for (int kk = 0; kk < 4; kk++) {
            uint32_t af[2][4], bf[8][2];
#pragma unroll
            for (int mt = 0; mt < 2; mt++) {
                int rb = wm * 32 + mt * 16;
                af[mt][0] = As[rb + g][kk * 8 + q4];
                af[mt][1] = As[rb + g + 8][kk * 8 + q4];
                af[mt][2] = As[rb + g][kk * 8 + q4 + 4];
                af[mt][3] = As[rb + g + 8][kk * 8 + q4 + 4];
            }
#pragma unroll
            for (int j = 0; j < 8; j++) {
                int nb = wn * 64 + j * 8 + g;
                bf[j][0] = Bs[nb][kk * 8 + q4];
                bf[j][1] = Bs[nb][kk * 8 + q4 + 4];
            }
#pragma unroll
            for (int mt = 0; mt < 2; mt++)
#pragma unroll
                for (int j = 0; j < 8; j++) mma_tf32(acc[mt][j], af[mt], bf[j]);
        }
        __syncthreads();
    }
#pragma unroll
    for (int mt = 0; mt < 2; mt++)
#pragma unroll
        for (int j = 0; j < 8; j++) {
            int row = bm + wm * 32 + mt * 16 + g;
            int col = bn + wn * 64 + j * 8 + 2 * q4;
            float2 v0 = make_float2(acc[mt][j][0], acc[mt][j][1]);
            float2 v1 = make_float2(acc[mt][j][2], acc[mt][j][3]);
            if (BIAS) {
                float b0 = bias[col], b1 = bias[col + 1];
                v0.x += b0; v0.y += b1; v1.x += b0; v1.y += b1;
            }
            *(float2*)&C[(size_t)row * N + col] = v0;
            *(float2*)&C[(size_t)(row + 8) * N + col] = v1;
        }
}

// Flash-style causal MQA attention, tf32 tensor cores.
// 256 thr = 8 warps; each warp owns 16 query rows. 64-key tiles from fused qkv buffer.
// q remap quirk: q[b,h,t,:] = qkv[b, h*128 + t/16, (t%16)*64 .. +64).
__global__ __launch_bounds__(256, 2) void attn_tc(const float* __restrict__ qkv,
                                                  float* __restrict__ y) {
    __shared__ uint32_t Ks[64][68];
    __shared__ uint32_t Vs[64][72];
    int bid = blockIdx.x;
    int qt = 15 - (bid >> 5);  // longest blocks first (LPT)
    int bh = bid & 31;
    int b = bh >> 4, h = bh & 15;
    int tid = threadIdx.x, lane = tid & 31, warp = tid >> 5;
    int g = lane >> 2, q4 = lane & 3;
    int r0 = qt * 128 + warp * 16 + g;
    int r1 = r0 + 8;

    const float* base = qkv + (size_t)b * T_ * NQKV;

    // Q fragments (remapped), pre-scaled by hs^-0.5 = 0.125
    uint32_t qa[8][4];
#pragma unroll
    for (int kk = 0; kk < 8; kk++) {
        int c0 = kk * 8 + q4;
        size_t a0 = (size_t)(h * 128 + (r0 >> 4)) * NQKV + (r0 & 15) * 64;
        size_t a1 = (size_t)(h * 128 + (r1 >> 4)) * NQKV + (r1 & 15) * 64;
        qa[kk][0] = f2tf(0.125f * base[a0 + c0]);
        qa[kk][1] = f2tf(0.125f * base[a1 + c0]);
        qa[kk][2] = f2tf(0.125f * base[a0 + c0 + 4]);
        qa[kk][3] = f2tf(0.125f * base[a1 + c0 + 4]);
    }

    float o[8][4];
#pragma unroll
    for (int j = 0; j < 8; j++)
#pragma unroll
        for (int e = 0; e < 4; e++) o[j][e] = 0.f;
    float m0 = -INFINITY, m1 = -INFINITY, l0 = 0.f, l1 = 0.f;

    int nkt = qt * 2 + 2;
    int wrmin = qt * 128 + warp * 16;
    int wrmax = wrmin + 15;
    int srcA = (lane & ~3) | (q4 >> 1);
    int srcB = srcA + 2;
    bool sel = (q4 & 1) != 0;

    for (int kt = 0; kt < nkt; kt++) {
        __syncthreads();
#pragma unroll
        for (int t = 0; t < 4; t++) {
            int idx = tid + t * 256;
            int r = idx >> 4, c4 = (idx & 15) * 4;
            size_t row = (size_t)(kt * 64 + r) * NQKV;
            float4 fk = *(const float4*)&base[row + 1024 + c4];
            *(uint4*)&Ks[r][c4] = make_uint4(f2tf(fk.x), f2tf(fk.y), f2tf(fk.z), f2tf(fk.w));
            float4 fv = *(const float4*)&base[row + 1088 + c4];
            *(uint4*)&Vs[r][c4] = make_uint4(f2tf(fv.x), f2tf(fv.y), f2tf(fv.z), f2tf(fv.w));
        }
        __syncthreads();
        int ktb = kt * 64;
        if (ktb > wrmax) continue;

        // S = Q K^T (pre-scaled)
        float s[8][4];
#pragma unroll
        for (int j = 0; j < 8; j++)
#pragma unroll
            for (int e = 0; e < 4; e++) s[j][e] = 0.f;
#pragma unroll
        for (int kk = 0; kk < 8; kk++) {
#pragma unroll
            for (int j = 0; j < 8; j++) {
                uint32_t bf[2];
                bf[0] = Ks[j * 8 + g][kk * 8 + q4];
                bf[1] = Ks[j * 8 + g][kk * 8 + q4 + 4];
                mma_tf32(s[j], qa[kk], bf);
            }
        }

        // mask + online softmax (s reused as float probabilities)
        bool needmask = (ktb + 63) > wrmin;
        float t0 = -INFINITY, t1 = -INFINITY;
#pragma unroll
        for (int j = 0; j < 8; j++) {
            if (needmask) {
                int tk = ktb + j * 8 + 2 * q4;
                if (tk > r0) s[j][0] = -INFINITY;
                if (tk + 1 > r0) s[j][1] = -INFINITY;
                if (tk > r1) s[j][2] = -INFINITY;
                if (tk + 1 > r1) s[j][3] = -INFINITY;
            }
            t0 = fmaxf(t0, fmaxf(s[j][0], s[j][1]));
            t1 = fmaxf(t1, fmaxf(s[j][2], s[j][3]));
        }
        t0 = fmaxf(t0, __shfl_xor_sync(0xffffffffu, t0, 1));
        t0 = fmaxf(t0, __shfl_xor_sync(0xffffffffu, t0, 2));
        t1 = fmaxf(t1, __shfl_xor_sync(0xffffffffu, t1, 1));
        t1 = fmaxf(t1, __shfl_xor_sync(0xffffffffu, t1, 2));
        float mn0 = fmaxf(m0, t0), mn1 = fmaxf(m1, t1);
        float cr0 = __expf(m0 - mn0), cr1 = __expf(m1 - mn1);
        m0 = mn0; m1 = mn1;
        l0 *= cr0; l1 *= cr1;
#pragma unroll
        for (int j = 0; j < 8; j++) {
            o[j][0] *= cr0; o[j][1] *= cr0;
            o[j][2] *= cr1; o[j][3] *= cr1;
        }
#pragma unroll
        for (int j = 0; j < 8; j++) {
            s[j][0] = __expf(s[j][0] - m0);
            s[j][1] = __expf(s[j][1] - m0);
            s[j][2] = __expf(s[j][2] - m1);
            s[j][3] = __expf(s[j][3] - m1);
            l0 += s[j][0] + s[j][1];
            l1 += s[j][2] + s[j][3];
        }

        // O += P V  (C-frag floats -> A-frag via quad shuffles, convert post-select)
#pragma unroll
        for (int kk = 0; kk < 8; kk++) {
            float x0 = __shfl_sync(0xffffffffu, s[kk][0], srcA);
            float x1 = __shfl_sync(0xffffffffu, s[kk][1], srcA);
            float x2 = __shfl_sync(0xffffffffu, s[kk][2], srcA);
            float x3 = __shfl_sync(0xffffffffu, s[kk][3], srcA);
            float y0 = __shfl_sync(0xffffffffu, s[kk][0], srcB);
            float y1 = __shfl_sync(0xffffffffu, s[kk][1], srcB);
            float y2 = __shfl_sync(0xffffffffu, s[kk][2], srcB);
            float y3 = __shfl_sync(0xffffffffu, s[kk][3], srcB);
            uint32_t pa[4];
            pa[0] = f2tf(sel ? x1 : x0);
            pa[1] = f2tf(sel ? x3 : x2);
            pa[2] = f2tf(sel ? y1 : y0);
            pa[3] = f2tf(sel ? y3 : y2);
#pragma unroll
            for (int j = 0; j < 8; j++) {
                uint32_t bf[2];
                bf[0] = Vs[kk * 8 + q4][j * 8 + g];
                bf[1] = Vs[kk * 8 + q4 + 4][j * 8 + g];
                mma_tf32(o[j], pa, bf);
            }
        }
    }

    l0 += __shfl_xor_sync(0xffffffffu, l0, 1);
    l0 += __shfl_xor_sync(0xffffffffu, l0, 2);
    l1 += __shfl_xor_sync(0xffffffffu, l1, 1);
    l1 += __shfl_xor_sync(0xffffffffu, l1, 2);
    float i0 = 1.f / l0, i1 = 1.f / l1;
    float* yb = y + (size_t)b * T_ * C_;
#pragma unroll
    for (int j = 0; j < 8; j++) {
        int col = h * 64 + j * 8 + 2 * q4;
        *(float2*)&yb[(size_t)r0 * C_ + col] = make_float2(o[j][0] * i0, o[j][1] * i0);
        *(float2*)&yb[(size_t)r1 * C_ + col] = make_float2(o[j][2] * i1, o[j][3] * i1);
    }
}

extern "C" void kernel_launch(void* const* d_in, const int* in_sizes, int n_in,
                              void* d_out, int out_size) {
    (void)in_sizes; (void)n_in; (void)out_size;
    const float* x  = (const float*)d_in[0];
    const float* Wk = (const float*)d_in[1];
    const float* Wv = (const float*)d_in[2];
    const float* Wq = (const float*)d_in[3];
    const float* Wp = (const float*)d_in[4];
    const float* bp = (const float*)d_in[5];
    float* out = (float*)d_out;

    float *wqkv, *qkvb, *yb;
    cudaGetSymbolAddress((void**)&wqkv, g_wqkv);
    cudaGetSymbolAddress((void**)&qkvb, g_qkv);
    cudaGetSymbolAddress((void**)&yb, g_y);

    // Concat weights, then one fused qkv projection: [4096,1152] = x @ [Wq‖Wk‖Wv].T
    copy_w<<<288, 256>>>(Wq, Wk, Wv, wqkv);
    gemm_tc<false><<<dim3(9, 32), 256>>>(x, wqkv, nullptr, qkvb, NQKV, 1024);
    // attention -> y [B,T,C] (head-transposed layout baked in)
    attn_tc<<<512, 256>>>(qkvb, yb);
    // out = y @ Wp.T + bp
    gemm_tc<true><<<dim3(8, 32), 256>>>(yb, Wp, bp, out, 1024, 1024);
}